// round 7
// baseline (speedup 1.0000x reference)
#include <cuda_runtime.h>

#define NB 64
#define NT 512
#define NI 1024
#define NH 1024
#define NG 4096   // 4*H
#define NBLK 128  // persistent blocks
#define PS2 516   // partial stride per gate-col (floats): 64*8 + 4

// ---------------- static scratch ----------------
__device__ float g_Wih[NG * NI];                 // gate-interleaved Wih
__device__ float g_bias[NG];                     // bih+bhh, interleaved
__device__ float g_Z[(size_t)NB * NT * NG];      // x-projection + bias (512 MB)
__device__ float g_Hfrag[2 * 128 * 128 * 8];     // [buf][kslot][m][pair-perm]; m<64 fwd, m>=64 bwd
__device__ unsigned g_cntA, g_cntB;
__device__ volatile unsigned g_phA, g_phB;

__device__ __forceinline__ float tf32r(float x) {
    unsigned u;
    asm("cvt.rna.tf32.f32 %0, %1;" : "=r"(u) : "f"(x));
    return __uint_as_float(u);
}
__device__ __forceinline__ unsigned fu(float x) { return __float_as_uint(x); }

__device__ __forceinline__ void mma8(float c[4], const unsigned a[4], const unsigned b[2]) {
    asm volatile(
        "mma.sync.aligned.m16n8k8.row.col.f32.tf32.tf32.f32 "
        "{%0,%1,%2,%3}, {%4,%5,%6,%7}, {%8,%9}, {%0,%1,%2,%3};\n"
        : "+f"(c[0]), "+f"(c[1]), "+f"(c[2]), "+f"(c[3])
        : "r"(a[0]), "r"(a[1]), "r"(a[2]), "r"(a[3]), "r"(b[0]), "r"(b[1]));
}

__device__ __forceinline__ float sigmf_(float x) { return 1.0f / (1.0f + __expf(-x)); }

// ---------------- fused prep: Wih permute + bias + H0 frag + barrier reset ------
__global__ void prep_all(const float* __restrict__ Wih,
                         const float* __restrict__ bih, const float* __restrict__ bhh,
                         const float* __restrict__ h0f, const float* __restrict__ h0b) {
    int idx = blockIdx.x * blockDim.x + threadIdx.x;   // < NG*1024
    int n = idx >> 10, k = idx & 1023;
    int j = n >> 2, g = n & 3;
    g_Wih[idx] = Wih[(g * NH + j) * 1024 + k];
    if (k == 0) g_bias[n] = bih[g * NH + j] + bhh[g * NH + j];
    if (idx < 128 * 1024) {   // H0 -> fragment-native layout, tf32-rounded
        int m = idx >> 10, jj = idx & 1023;
        float h = (m < 64) ? h0f[m * NH + jj] : h0b[(m - 64) * NH + jj];
        int p = ((jj & 3) << 1) | ((jj >> 2) & 1);
        g_Hfrag[((size_t)(jj >> 3) * 128 + m) * 8 + p] = tf32r(h);
    }
    if (idx == 0) { g_cntA = 0; g_cntB = 0; g_phA = 0; g_phB = 0; }
}

// ---------------- phase 1: Z = X @ Wih^T + bias ----------------
__global__ __launch_bounds__(256) void zproj_kernel(const float* __restrict__ X) {
    __shared__ float As[128 * 20];
    __shared__ float Bs2[128 * 20];
    int tid = threadIdx.x;
    int row0 = blockIdx.y * 128;
    int n0 = blockIdx.x * 128;
    const float* Ag = X + (size_t)row0 * NI;
    const float* Bg = g_Wih + (size_t)n0 * NI;

    int lr = tid >> 2;
    int lc = (tid & 3) * 4;
    int w = tid >> 5, lane = tid & 31, gid = lane >> 2, tig = lane & 3;
    int wm = (w >> 2) * 64, wn = (w & 3) * 32;

    float c[4][4][4];
#pragma unroll
    for (int mi = 0; mi < 4; mi++)
#pragma unroll
        for (int ni = 0; ni < 4; ni++)
#pragma unroll
            for (int q = 0; q < 4; q++) c[mi][ni][q] = 0.f;

    float4 pa0 = *(const float4*)(Ag + (size_t)lr * NI + lc);
    float4 pa1 = *(const float4*)(Ag + (size_t)(lr + 64) * NI + lc);
    float4 pb0 = *(const float4*)(Bg + (size_t)lr * NI + lc);
    float4 pb1 = *(const float4*)(Bg + (size_t)(lr + 64) * NI + lc);

    for (int kk = 0; kk < NI; kk += 16) {
        *(float4*)&As[lr * 20 + lc] = make_float4(tf32r(pa0.x), tf32r(pa0.y), tf32r(pa0.z), tf32r(pa0.w));
        *(float4*)&As[(lr + 64) * 20 + lc] = make_float4(tf32r(pa1.x), tf32r(pa1.y), tf32r(pa1.z), tf32r(pa1.w));
        *(float4*)&Bs2[lr * 20 + lc] = make_float4(tf32r(pb0.x), tf32r(pb0.y), tf32r(pb0.z), tf32r(pb0.w));
        *(float4*)&Bs2[(lr + 64) * 20 + lc] = make_float4(tf32r(pb1.x), tf32r(pb1.y), tf32r(pb1.z), tf32r(pb1.w));
        __syncthreads();
        if (kk + 16 < NI) {
            pa0 = *(const float4*)(Ag + (size_t)lr * NI + kk + 16 + lc);
            pa1 = *(const float4*)(Ag + (size_t)(lr + 64) * NI + kk + 16 + lc);
            pb0 = *(const float4*)(Bg + (size_t)lr * NI + kk + 16 + lc);
            pb1 = *(const float4*)(Bg + (size_t)(lr + 64) * NI + kk + 16 + lc);
        }
#pragma unroll
        for (int k8 = 0; k8 < 16; k8 += 8) {
            unsigned a[4][4], b[4][2];
#pragma unroll
            for (int mi = 0; mi < 4; mi++) {
                int rb = wm + mi * 16 + gid;
                a[mi][0] = fu(As[rb * 20 + k8 + tig]);
                a[mi][1] = fu(As[(rb + 8) * 20 + k8 + tig]);
                a[mi][2] = fu(As[rb * 20 + k8 + 4 + tig]);
                a[mi][3] = fu(As[(rb + 8) * 20 + k8 + 4 + tig]);
            }
#pragma unroll
            for (int ni = 0; ni < 4; ni++) {
                int nb = wn + ni * 8 + gid;
                b[ni][0] = fu(Bs2[nb * 20 + k8 + tig]);
                b[ni][1] = fu(Bs2[nb * 20 + k8 + 4 + tig]);
            }
#pragma unroll
            for (int mi = 0; mi < 4; mi++)
#pragma unroll
                for (int ni = 0; ni < 4; ni++) mma8(c[mi][ni], a[mi], b[ni]);
        }
        __syncthreads();
    }

#pragma unroll
    for (int mi = 0; mi < 4; mi++)
#pragma unroll
        for (int ni = 0; ni < 4; ni++) {
            int r = row0 + wm + mi * 16 + gid;
            int col = n0 + wn + ni * 8 + tig * 2;
            float b0 = g_bias[col], b1 = g_bias[col + 1];
            size_t o = (size_t)r * NG + col;
            g_Z[o] = c[mi][ni][0] + b0;
            g_Z[o + 1] = c[mi][ni][1] + b1;
            o += (size_t)8 * NG;
            g_Z[o] = c[mi][ni][2] + b0;
            g_Z[o + 1] = c[mi][ni][3] + b1;
        }
}

// ---------------- split grid barrier (arrive / wait decoupled) ----------------
__device__ __forceinline__ void bar_arrive(unsigned* cnt, volatile unsigned* ph, unsigned target) {
    __syncthreads();                 // also orders epilogue smem reads vs next phase's dumps
    if (threadIdx.x == 0) {
        __threadfence();             // make H writes visible before signaling
        if (atomicAdd(cnt, 1u) == NBLK - 1) {
            *cnt = 0;
            __threadfence();
            *ph = target;
        }
    }
}
__device__ __forceinline__ void bar_wait(volatile unsigned* ph, unsigned target) {
    if (threadIdx.x == 0) {
        while (*ph < target) { __nanosleep(40); }
        __threadfence();
    }
    __syncthreads();
}

// ---------------- persistent recurrent kernel: dual-chain pipelined ----------------
// Block b owns gate cols [32b,32b+32) (hidden units 8b..8b+8); Whh fragments in
// REGISTERS (warp w owns K-chunk [128w,128w+128)). Each step = fwd phase (batches
// 0..63, barrier A) then bwd phase (batches 64..127, barrier B); each barrier's
// propagation hides under the other direction's compute.
__global__ __launch_bounds__(256, 1) void lstm_persistent(float* __restrict__ out,
                                                          const float* __restrict__ Whh,
                                                          const float* __restrict__ c0f,
                                                          const float* __restrict__ c0b) {
    extern __shared__ float part[];   // 32 gate-cols x PS2 ; part[gc*PS2 + ml*8 + w]

    const int b = blockIdx.x, tid = threadIdx.x;
    const int w = tid >> 5, lane = tid & 31, gid = lane >> 2, tig = lane & 3;

    // one-time: A fragments (gate-permuted Whh rows, tf32) into registers
    unsigned Areg[2][16][4];
#pragma unroll
    for (int mt = 0; mt < 2; mt++)
#pragma unroll
        for (int ks = 0; ks < 16; ks++)
#pragma unroll
            for (int q = 0; q < 4; q++) {
                int pr = b * 32 + mt * 16 + gid + 8 * (q & 1);   // gate-interleaved row
                int orow = (pr & 3) * NH + (pr >> 2);            // original Whh row
                int col = (w * 16 + ks) * 8 + tig + 4 * (q >> 1);
                Areg[mt][ks][q] = fu(tf32r(Whh[(size_t)orow * NH + col]));
            }

    // C state in registers: item (dir, it) -> batch ml=(it*256+tid)>>3, unit u=(it*256+tid)&7
    float Creg[2][2];
#pragma unroll
    for (int dir = 0; dir < 2; dir++)
#pragma unroll
        for (int it = 0; it < 2; it++) {
            int idx = it * 256 + tid, ml = idx >> 3, u = idx & 7, j = b * 8 + u;
            Creg[dir][it] = dir ? c0b[ml * NH + j] : c0f[ml * NH + j];
        }

    const size_t OB = (size_t)NB * NT * 2048;

    for (int t = 0; t < NT; t++) {
#pragma unroll
        for (int dir = 0; dir < 2; dir++) {
            const int m0 = dir << 6;

            // Z prefetch (streaming; consumed in epilogue)
            float4 zreg[2];
#pragma unroll
            for (int it = 0; it < 2; it++) {
                int idx = it * 256 + tid, ml = idx >> 3, u = idx & 7;
                size_t zrow = dir ? ((size_t)ml * NT + (NT - 1 - t)) : ((size_t)ml * NT + t);
                zreg[it] = __ldcs((const float4*)&g_Z[zrow * NG + b * 32 + u * 4]);
            }

            // main loop: zero LDS; 16 batched LDGs per nt-tile
            const float* Hp = g_Hfrag + (size_t)(t & 1) * 131072
                              + (size_t)w * 16 * 1024 + (m0 + gid) * 8 + tig * 2;
            for (int nt = 0; nt < 8; nt++) {
                float2 f[16];
#pragma unroll
                for (int ks = 0; ks < 16; ks++)
                    f[ks] = __ldcg((const float2*)(Hp + (size_t)ks * 1024 + nt * 64));
                float acc0[4] = {0.f, 0.f, 0.f, 0.f}, acc1[4] = {0.f, 0.f, 0.f, 0.f};
#pragma unroll
                for (int ks = 0; ks < 16; ks++) {
                    unsigned bb[2] = {fu(f[ks].x), fu(f[ks].y)};
                    mma8(acc0, Areg[0][ks], bb);
                    mma8(acc1, Areg[1][ks], bb);
                }
                int mb = nt * 8 + 2 * tig;
                part[gid * PS2 + mb * 8 + w] = acc0[0];
                part[gid * PS2 + (mb + 1) * 8 + w] = acc0[1];
                part[(gid + 8) * PS2 + mb * 8 + w] = acc0[2];
                part[(gid + 8) * PS2 + (mb + 1) * 8 + w] = acc0[3];
                part[(gid + 16) * PS2 + mb * 8 + w] = acc1[0];
                part[(gid + 16) * PS2 + (mb + 1) * 8 + w] = acc1[1];
                part[(gid + 24) * PS2 + mb * 8 + w] = acc1[2];
                part[(gid + 24) * PS2 + (mb + 1) * 8 + w] = acc1[3];
            }
            __syncthreads();

            // epilogue: reduce 8 partials + LSTM pointwise
            float* Hn = g_Hfrag + (size_t)((t + 1) & 1) * 131072 + (size_t)b * 1024;
#pragma unroll
            for (int it = 0; it < 2; it++) {
                int idx = it * 256 + tid, ml = idx >> 3, u = idx & 7, j = b * 8 + u;
                float s[4];
#pragma unroll
                for (int g = 0; g < 4; g++) {
                    const float* p = &part[(4 * u + g) * PS2 + ml * 8];
                    float4 p0 = *(const float4*)p;
                    float4 p1 = *(const float4*)(p + 4);
                    s[g] = ((p0.x + p0.y) + (p0.z + p0.w)) + ((p1.x + p1.y) + (p1.z + p1.w));
                }
                float4 z = zreg[it];
                float iv = sigmf_(s[0] + z.x);
                float fv = sigmf_(s[1] + z.y);
                float gv = tanhf(s[2] + z.z);
                float ov = sigmf_(s[3] + z.w);
                float cv = fv * Creg[dir][it] + iv * gv;
                Creg[dir][it] = cv;
                float h = ov * tanhf(cv);
                int p = ((u & 3) << 1) | (u >> 2);
                Hn[(m0 + ml) * 8 + p] = tf32r(h);
                if (dir == 0) {
                    out[((size_t)ml * NT + t) * 2048 + j] = h;
                    out[((size_t)(63 - ml) * NT + t) * 2048 + 1024 + j] = h;
                    if (t == NT - 1) out[OB + (size_t)ml * 2048 + j] = h;
                } else if (t == NT - 1) {
                    out[OB + (size_t)ml * 2048 + 1024 + j] = h;
                }
            }

            if (dir == 0) {
                bar_arrive(&g_cntA, &g_phA, (unsigned)(t + 1));
                bar_wait(&g_phB, (unsigned)t);          // Hb(t) ready (arrived last step)
            } else {
                bar_arrive(&g_cntB, &g_phB, (unsigned)(t + 1));
                bar_wait(&g_phA, (unsigned)(t + 1));    // Hf(t+1) ready for next fwd phase
            }
        }
    }

    // c_i from registers
#pragma unroll
    for (int dir = 0; dir < 2; dir++)
#pragma unroll
        for (int it = 0; it < 2; it++) {
            int idx = it * 256 + tid, ml = idx >> 3, u = idx & 7, j = b * 8 + u;
            out[OB + 131072 + (size_t)ml * 2048 + dir * 1024 + j] = Creg[dir][it];
        }
}

extern "C" void kernel_launch(void* const* d_in, const int* in_sizes, int n_in,
                              void* d_out, int out_size) {
    const float* x     = (const float*)d_in[0];
    const float* Wih_f = (const float*)d_in[1];
    const float* Whh_f = (const float*)d_in[2];
    const float* bih_f = (const float*)d_in[3];
    const float* bhh_f = (const float*)d_in[4];
    // d_in[5..8] (_b weights) are unused by the reference computation.
    const float* h0f   = (const float*)d_in[9];
    const float* c0f   = (const float*)d_in[10];
    const float* h0b   = (const float*)d_in[11];
    const float* c0b   = (const float*)d_in[12];
    float* out = (float*)d_out;

    const int smem_bytes = 32 * PS2 * 4;   // 66048
    cudaFuncSetAttribute(lstm_persistent, cudaFuncAttributeMaxDynamicSharedMemorySize, smem_bytes);

    prep_all<<<(NG * NI) / 256, 256>>>(Wih_f, bih_f, bhh_f, h0f, h0b);

    dim3 zg(NG / 128, (NB * NT) / 128);   // (32, 256)
    zproj_kernel<<<zg, 256>>>(x);

    lstm_persistent<<<NBLK, 256, smem_bytes>>>(out, Whh_f, c0f, c0b);
}

// round 8
// speedup vs baseline: 1.9170x; 1.9170x over previous
#include <cuda_runtime.h>
#include <cuda_fp16.h>

#define NB 64
#define NT 512
#define NI 1024
#define NH 1024
#define NG 4096   // 4*H
#define NBLK 128  // persistent blocks
#define PS 1028   // partial stride per gate-col (floats): %4==0 (float4), %32==4 (bank skew)

// ---------------- static scratch ----------------
__device__ float g_Wih[NG * NI];                 // gate-interleaved Wih (for zproj)
__device__ float g_bias[NG];                     // bih+bhh, interleaved
__device__ float g_Z[(size_t)NB * NT * NG];      // x-projection + bias (512 MB)
// H state, fp16, fragment-native for m16n8k16 B-operand:
// record (kslot=k/16, m): 16 halves, position 4t..4t+3 = k = {2t, 2t+1, 2t+8, 2t+9}
__device__ __half g_Hfrag[2 * 64 * 128 * 16];
__device__ unsigned g_barcnt;
__device__ volatile unsigned g_barphase;

__device__ __forceinline__ float tf32r(float x) {
    unsigned u;
    asm("cvt.rna.tf32.f32 %0, %1;" : "=r"(u) : "f"(x));
    return __uint_as_float(u);
}
__device__ __forceinline__ unsigned fu(float x) { return __float_as_uint(x); }
__device__ __forceinline__ unsigned h2u(__half2 h) { return *reinterpret_cast<unsigned*>(&h); }

// tf32 k8 MMA (zproj)
__device__ __forceinline__ void mma8(float c[4], const unsigned a[4], const unsigned b[2]) {
    asm volatile(
        "mma.sync.aligned.m16n8k8.row.col.f32.tf32.tf32.f32 "
        "{%0,%1,%2,%3}, {%4,%5,%6,%7}, {%8,%9}, {%0,%1,%2,%3};\n"
        : "+f"(c[0]), "+f"(c[1]), "+f"(c[2]), "+f"(c[3])
        : "r"(a[0]), "r"(a[1]), "r"(a[2]), "r"(a[3]), "r"(b[0]), "r"(b[1]));
}

// fp16 k16 MMA (recurrent)
__device__ __forceinline__ void mma16(float c[4], const unsigned a[4], unsigned b0, unsigned b1) {
    asm volatile(
        "mma.sync.aligned.m16n8k16.row.col.f32.f16.f16.f32 "
        "{%0,%1,%2,%3}, {%4,%5,%6,%7}, {%8,%9}, {%0,%1,%2,%3};\n"
        : "+f"(c[0]), "+f"(c[1]), "+f"(c[2]), "+f"(c[3])
        : "r"(a[0]), "r"(a[1]), "r"(a[2]), "r"(a[3]), "r"(b0), "r"(b1));
}

__device__ __forceinline__ float sigmf_(float x) { return 1.0f / (1.0f + __expf(-x)); }

// half index within a 16-half H record for hidden-in-slot kl (0..15)
__device__ __forceinline__ int hidx_of(int kl) {
    return 4 * ((kl & 7) >> 1) + ((kl >> 3) << 1) + (kl & 1);
}

// ---------------- fused prep: Wih permute + bias + H0 frag + barrier reset ------
__global__ void prep_all(const float* __restrict__ Wih,
                         const float* __restrict__ bih, const float* __restrict__ bhh,
                         const float* __restrict__ h0f, const float* __restrict__ h0b) {
    int idx = blockIdx.x * blockDim.x + threadIdx.x;   // < NG*1024
    int n = idx >> 10, k = idx & 1023;
    int j = n >> 2, g = n & 3;
    g_Wih[idx] = Wih[(g * NH + j) * 1024 + k];
    if (k == 0) g_bias[n] = bih[g * NH + j] + bhh[g * NH + j];
    if (idx < 128 * 1024) {   // H0 -> fp16 fragment-native
        int m = idx >> 10, jj = idx & 1023;
        float h = (m < 64) ? h0f[m * NH + jj] : h0b[(m - 64) * NH + jj];
        g_Hfrag[(size_t)((jj >> 4) * 128 + m) * 16 + hidx_of(jj & 15)] = __float2half_rn(h);
    }
    if (idx == 0) { g_barcnt = 0; g_barphase = 0; }
}

// ---------------- phase 1: Z = X @ Wih^T + bias ----------------
__global__ __launch_bounds__(256) void zproj_kernel(const float* __restrict__ X) {
    __shared__ float As[128 * 20];
    __shared__ float Bs2[128 * 20];
    int tid = threadIdx.x;
    int row0 = blockIdx.y * 128;
    int n0 = blockIdx.x * 128;
    const float* Ag = X + (size_t)row0 * NI;
    const float* Bg = g_Wih + (size_t)n0 * NI;

    int lr = tid >> 2;
    int lc = (tid & 3) * 4;
    int w = tid >> 5, lane = tid & 31, gid = lane >> 2, tig = lane & 3;
    int wm = (w >> 2) * 64, wn = (w & 3) * 32;

    float c[4][4][4];
#pragma unroll
    for (int mi = 0; mi < 4; mi++)
#pragma unroll
        for (int ni = 0; ni < 4; ni++)
#pragma unroll
            for (int q = 0; q < 4; q++) c[mi][ni][q] = 0.f;

    float4 pa0 = *(const float4*)(Ag + (size_t)lr * NI + lc);
    float4 pa1 = *(const float4*)(Ag + (size_t)(lr + 64) * NI + lc);
    float4 pb0 = *(const float4*)(Bg + (size_t)lr * NI + lc);
    float4 pb1 = *(const float4*)(Bg + (size_t)(lr + 64) * NI + lc);

    for (int kk = 0; kk < NI; kk += 16) {
        *(float4*)&As[lr * 20 + lc] = make_float4(tf32r(pa0.x), tf32r(pa0.y), tf32r(pa0.z), tf32r(pa0.w));
        *(float4*)&As[(lr + 64) * 20 + lc] = make_float4(tf32r(pa1.x), tf32r(pa1.y), tf32r(pa1.z), tf32r(pa1.w));
        *(float4*)&Bs2[lr * 20 + lc] = make_float4(tf32r(pb0.x), tf32r(pb0.y), tf32r(pb0.z), tf32r(pb0.w));
        *(float4*)&Bs2[(lr + 64) * 20 + lc] = make_float4(tf32r(pb1.x), tf32r(pb1.y), tf32r(pb1.z), tf32r(pb1.w));
        __syncthreads();
        if (kk + 16 < NI) {
            pa0 = *(const float4*)(Ag + (size_t)lr * NI + kk + 16 + lc);
            pa1 = *(const float4*)(Ag + (size_t)(lr + 64) * NI + kk + 16 + lc);
            pb0 = *(const float4*)(Bg + (size_t)lr * NI + kk + 16 + lc);
            pb1 = *(const float4*)(Bg + (size_t)(lr + 64) * NI + kk + 16 + lc);
        }
#pragma unroll
        for (int k8 = 0; k8 < 16; k8 += 8) {
            unsigned a[4][4], b[4][2];
#pragma unroll
            for (int mi = 0; mi < 4; mi++) {
                int rb = wm + mi * 16 + gid;
                a[mi][0] = fu(As[rb * 20 + k8 + tig]);
                a[mi][1] = fu(As[(rb + 8) * 20 + k8 + tig]);
                a[mi][2] = fu(As[rb * 20 + k8 + 4 + tig]);
                a[mi][3] = fu(As[(rb + 8) * 20 + k8 + 4 + tig]);
            }
#pragma unroll
            for (int ni = 0; ni < 4; ni++) {
                int nb = wn + ni * 8 + gid;
                b[ni][0] = fu(Bs2[nb * 20 + k8 + tig]);
                b[ni][1] = fu(Bs2[nb * 20 + k8 + 4 + tig]);
            }
#pragma unroll
            for (int mi = 0; mi < 4; mi++)
#pragma unroll
                for (int ni = 0; ni < 4; ni++) mma8(c[mi][ni], a[mi], b[ni]);
        }
        __syncthreads();
    }

#pragma unroll
    for (int mi = 0; mi < 4; mi++)
#pragma unroll
        for (int ni = 0; ni < 4; ni++) {
            int r = row0 + wm + mi * 16 + gid;
            int col = n0 + wn + ni * 8 + tig * 2;
            float b0 = g_bias[col], b1 = g_bias[col + 1];
            size_t o = (size_t)r * NG + col;
            g_Z[o] = c[mi][ni][0] + b0;
            g_Z[o + 1] = c[mi][ni][1] + b1;
            o += (size_t)8 * NG;
            g_Z[o] = c[mi][ni][2] + b0;
            g_Z[o + 1] = c[mi][ni][3] + b1;
        }
}

// ---------------- grid barrier (single, per step) ----------------
__device__ __forceinline__ void grid_bar(unsigned target) {
    __syncthreads();
    if (threadIdx.x == 0) {
        __threadfence();
        unsigned old = atomicAdd(&g_barcnt, 1u);
        if (old == NBLK - 1) {
            g_barcnt = 0;
            __threadfence();
            g_barphase = target;
        } else {
            while (g_barphase < target) { __nanosleep(40); }
        }
        __threadfence();
    }
    __syncthreads();
}

// ---------------- persistent recurrent kernel: fp16, K-split, weights in regs ----
// Block b: gate cols [32b,32b+32) (hidden units 8b..8b+8). Warp w owns K-chunk
// [128w,128w+128) = 8 k16 slots; Whh fragments (fp16) in registers, loaded once.
// Per step: warp computes PARTIAL 32x128 gate tile (B = fp16 H fragments straight
// from L2, one uint2 per B-frag), partials -> smem, epilogue reduces + pointwise.
__global__ __launch_bounds__(256, 1) void lstm_persistent(float* __restrict__ out,
                                                          const float* __restrict__ Whh,
                                                          const float* __restrict__ c0f,
                                                          const float* __restrict__ c0b) {
    extern __shared__ float part[];   // 32 gate-cols x PS ; part[gc*PS + m*8 + w]

    const int b = blockIdx.x, tid = threadIdx.x;
    const int w = tid >> 5, lane = tid & 31, gid = lane >> 2, tig = lane & 3;

    // one-time: fp16 A fragments (gate-permuted Whh rows) into registers
    unsigned Areg[2][8][4];
#pragma unroll
    for (int mt = 0; mt < 2; mt++)
#pragma unroll
        for (int ks = 0; ks < 8; ks++)
#pragma unroll
            for (int q = 0; q < 4; q++) {
                int pr = b * 32 + mt * 16 + gid + 8 * (q & 1);   // gate-interleaved row
                int orow = (pr & 3) * NH + (pr >> 2);            // original Whh row
                int kc = (w * 8 + ks) * 16 + 2 * tig + 8 * (q >> 1);
                Areg[mt][ks][q] = h2u(__floats2half2_rn(Whh[(size_t)orow * NH + kc],
                                                        Whh[(size_t)orow * NH + kc + 1]));
            }

    // C state in registers: item it -> (m = (it*256+tid)>>3, u = (it*256+tid)&7)
    float Creg[4];
#pragma unroll
    for (int it = 0; it < 4; it++) {
        int idx = it * 256 + tid, m = idx >> 3, u = idx & 7, j = b * 8 + u;
        Creg[it] = (m < 64) ? c0f[m * NH + j] : c0b[(m - 64) * NH + j];
    }

    const size_t OB = (size_t)NB * NT * 2048;
    // lane-constant base into H records (halves): (kslot=w*8, m=gid) record + tig*4
    const size_t hlane = ((size_t)w * 8 * 128 + gid) * 16 + tig * 4;

    for (int t = 0; t < NT; t++) {
        const __half* Hb = g_Hfrag + (size_t)(t & 1) * 131072 + hlane;

        // Z prefetch (streaming; consumed in epilogue)
        float4 zreg[4];
#pragma unroll
        for (int it = 0; it < 4; it++) {
            int idx = it * 256 + tid, m = idx >> 3, u = idx & 7;
            size_t zrow = (m < 64) ? ((size_t)m * NT + t) : ((size_t)(m - 64) * NT + (NT - 1 - t));
            zreg[it] = __ldcs((const float4*)&g_Z[zrow * NG + b * 32 + u * 4]);
        }

        // ---- main loop: 8 pair-iterations, each = 2 nt-tiles (16 batches) ----
        // double-buffered prefetch: loads for pair p+1 issue before MMAs of pair p
        uint2 fb[2][16];
#pragma unroll
        for (int q = 0; q < 16; q++) {   // pair 0: nt = 0,1
            int nt = q >> 3, ks = q & 7;
            fb[0][q] = __ldcg((const uint2*)(Hb + (size_t)ks * 2048 + nt * 128));
        }
#pragma unroll
        for (int p = 0; p < 8; p++) {
            const int cur = p & 1;
            if (p < 7) {
#pragma unroll
                for (int q = 0; q < 16; q++) {
                    int nt = (p + 1) * 2 + (q >> 3), ks = q & 7;
                    fb[cur ^ 1][q] = __ldcg((const uint2*)(Hb + (size_t)ks * 2048 + nt * 128));
                }
            }
            float acc[2][2][4];
#pragma unroll
            for (int n2 = 0; n2 < 2; n2++)
#pragma unroll
                for (int mt = 0; mt < 2; mt++)
#pragma unroll
                    for (int q = 0; q < 4; q++) acc[n2][mt][q] = 0.f;
#pragma unroll
            for (int ks = 0; ks < 8; ks++) {
#pragma unroll
                for (int n2 = 0; n2 < 2; n2++) {
                    uint2 bb = fb[cur][n2 * 8 + ks];
                    mma16(acc[n2][0], Areg[0][ks], bb.x, bb.y);
                    mma16(acc[n2][1], Areg[1][ks], bb.x, bb.y);
                }
            }
            // partials -> smem: part[gc*PS + m*8 + w]
#pragma unroll
            for (int n2 = 0; n2 < 2; n2++) {
                int mb = (p * 2 + n2) * 8 + 2 * tig;
#pragma unroll
                for (int mt = 0; mt < 2; mt++) {
                    int gc = mt * 16 + gid;
                    part[gc * PS + mb * 8 + w] = acc[n2][mt][0];
                    part[gc * PS + (mb + 1) * 8 + w] = acc[n2][mt][1];
                    part[(gc + 8) * PS + mb * 8 + w] = acc[n2][mt][2];
                    part[(gc + 8) * PS + (mb + 1) * 8 + w] = acc[n2][mt][3];
                }
            }
        }
        __syncthreads();

        // ---- epilogue: reduce 8 partials + LSTM pointwise ----
        __half* Hn = g_Hfrag + (size_t)((t + 1) & 1) * 131072;
#pragma unroll
        for (int it = 0; it < 4; it++) {
            int idx = it * 256 + tid, m = idx >> 3, u = idx & 7, j = b * 8 + u;
            float s[4];
#pragma unroll
            for (int g = 0; g < 4; g++) {
                const float* p = &part[(4 * u + g) * PS + m * 8];
                float4 p0 = *(const float4*)p;
                float4 p1 = *(const float4*)(p + 4);
                s[g] = ((p0.x + p0.y) + (p0.z + p0.w)) + ((p1.x + p1.y) + (p1.z + p1.w));
            }
            float4 z = zreg[it];
            float iv = sigmf_(s[0] + z.x);
            float fv = sigmf_(s[1] + z.y);
            float gv = tanhf(s[2] + z.z);
            float ov = sigmf_(s[3] + z.w);
            float cv = fv * Creg[it] + iv * gv;
            Creg[it] = cv;
            float h = ov * tanhf(cv);
            Hn[(size_t)((j >> 4) * 128 + m) * 16 + hidx_of(j & 15)] = __float2half_rn(h);
            if (m < 64) {
                out[((size_t)m * NT + t) * 2048 + j] = h;
                out[((size_t)(63 - m) * NT + t) * 2048 + 1024 + j] = h;
                if (t == NT - 1) out[OB + (size_t)m * 2048 + j] = h;
            } else if (t == NT - 1) {
                out[OB + (size_t)(m - 64) * 2048 + 1024 + j] = h;
            }
        }

        grid_bar((unsigned)(t + 1));   // leading __syncthreads protects part reuse
    }

    // c_i from registers
#pragma unroll
    for (int it = 0; it < 4; it++) {
        int idx = it * 256 + tid, m = idx >> 3, u = idx & 7, j = b * 8 + u;
        size_t o = OB + 131072 + ((m < 64) ? ((size_t)m * 2048 + j)
                                           : ((size_t)(m - 64) * 2048 + 1024 + j));
        out[o] = Creg[it];
    }
}

extern "C" void kernel_launch(void* const* d_in, const int* in_sizes, int n_in,
                              void* d_out, int out_size) {
    const float* x     = (const float*)d_in[0];
    const float* Wih_f = (const float*)d_in[1];
    const float* Whh_f = (const float*)d_in[2];
    const float* bih_f = (const float*)d_in[3];
    const float* bhh_f = (const float*)d_in[4];
    // d_in[5..8] (_b weights) are unused by the reference computation.
    const float* h0f   = (const float*)d_in[9];
    const float* c0f   = (const float*)d_in[10];
    const float* h0b   = (const float*)d_in[11];
    const float* c0b   = (const float*)d_in[12];
    float* out = (float*)d_out;

    const int smem_bytes = 32 * PS * 4;   // 131584
    cudaFuncSetAttribute(lstm_persistent, cudaFuncAttributeMaxDynamicSharedMemorySize, smem_bytes);

    prep_all<<<(NG * NI) / 256, 256>>>(Wih_f, bih_f, bhh_f, h0f, h0b);

    dim3 zg(NG / 128, (NB * NT) / 128);   // (32, 256)
    zproj_kernel<<<zg, 256>>>(x);

    lstm_persistent<<<NBLK, 256, smem_bytes>>>(out, Whh_f, c0f, c0b);
}

// round 9
// speedup vs baseline: 2.0117x; 1.0494x over previous
#include <cuda_runtime.h>
#include <cuda_fp16.h>

#define NB 64
#define NT 512
#define NI 1024
#define NH 1024
#define NG 4096   // 4*H
#define NBLK 128  // persistent blocks = 64 gate-groups x 2 batch-halves
#define PS2 516   // partial stride per gate-col (floats): 64*8 + 4 (bank skew)

// ---------------- static scratch ----------------
__device__ float g_Wih[NG * NI];                 // gate-interleaved Wih (for zproj)
__device__ float g_bias[NG];                     // bih+bhh, interleaved
__device__ float g_Z[(size_t)NB * NT * NG];      // x-projection + bias (512 MB)
// H state, fp16, fragment-native for m16n8k16 B-operand:
// record (kslot=k/16, m): 16 halves, position 4q..4q+3 = k = {2q, 2q+1, 2q+8, 2q+9}
__device__ __half g_Hfrag[2 * 64 * 128 * 16];
__device__ int g_flags[NBLK * 32];               // release flags, 128B apart

__device__ __forceinline__ float tf32r(float x) {
    unsigned u;
    asm("cvt.rna.tf32.f32 %0, %1;" : "=r"(u) : "f"(x));
    return __uint_as_float(u);
}
__device__ __forceinline__ unsigned fu(float x) { return __float_as_uint(x); }
__device__ __forceinline__ unsigned h2u(__half2 h) { return *reinterpret_cast<unsigned*>(&h); }

// tf32 k8 MMA (zproj)
__device__ __forceinline__ void mma8(float c[4], const unsigned a[4], const unsigned b[2]) {
    asm volatile(
        "mma.sync.aligned.m16n8k8.row.col.f32.tf32.tf32.f32 "
        "{%0,%1,%2,%3}, {%4,%5,%6,%7}, {%8,%9}, {%0,%1,%2,%3};\n"
        : "+f"(c[0]), "+f"(c[1]), "+f"(c[2]), "+f"(c[3])
        : "r"(a[0]), "r"(a[1]), "r"(a[2]), "r"(a[3]), "r"(b[0]), "r"(b[1]));
}

// fp16 k16 MMA (recurrent)
__device__ __forceinline__ void mma16(float c[4], const unsigned a[4], unsigned b0, unsigned b1) {
    asm volatile(
        "mma.sync.aligned.m16n8k16.row.col.f32.f16.f16.f32 "
        "{%0,%1,%2,%3}, {%4,%5,%6,%7}, {%8,%9}, {%0,%1,%2,%3};\n"
        : "+f"(c[0]), "+f"(c[1]), "+f"(c[2]), "+f"(c[3])
        : "r"(a[0]), "r"(a[1]), "r"(a[2]), "r"(a[3]), "r"(b0), "r"(b1));
}

__device__ __forceinline__ float sigmf_(float x) { return 1.0f / (1.0f + __expf(-x)); }

// half index within a 16-half H record for hidden-in-slot kl (0..15)
__device__ __forceinline__ int hidx_of(int kl) {
    return 4 * ((kl & 7) >> 1) + ((kl >> 3) << 1) + (kl & 1);
}

// ---------------- fused prep: Wih permute + bias + H0 frag + flag reset ------
__global__ void prep_all(const float* __restrict__ Wih,
                         const float* __restrict__ bih, const float* __restrict__ bhh,
                         const float* __restrict__ h0f, const float* __restrict__ h0b) {
    int idx = blockIdx.x * blockDim.x + threadIdx.x;   // < NG*1024
    int n = idx >> 10, k = idx & 1023;
    int j = n >> 2, g = n & 3;
    g_Wih[idx] = Wih[(g * NH + j) * 1024 + k];
    if (k == 0) g_bias[n] = bih[g * NH + j] + bhh[g * NH + j];
    if (idx < 128 * 1024) {   // H0 -> fp16 fragment-native
        int m = idx >> 10, jj = idx & 1023;
        float h = (m < 64) ? h0f[m * NH + jj] : h0b[(m - 64) * NH + jj];
        g_Hfrag[(size_t)((jj >> 4) * 128 + m) * 16 + hidx_of(jj & 15)] = __float2half_rn(h);
    }
    if (idx < NBLK * 32) g_flags[idx] = 0;
}

// ---------------- phase 1: Z = X @ Wih^T + bias ----------------
__global__ __launch_bounds__(256) void zproj_kernel(const float* __restrict__ X) {
    __shared__ float As[128 * 20];
    __shared__ float Bs2[128 * 20];
    int tid = threadIdx.x;
    int row0 = blockIdx.y * 128;
    int n0 = blockIdx.x * 128;
    const float* Ag = X + (size_t)row0 * NI;
    const float* Bg = g_Wih + (size_t)n0 * NI;

    int lr = tid >> 2;
    int lc = (tid & 3) * 4;
    int w = tid >> 5, lane = tid & 31, gid = lane >> 2, tig = lane & 3;
    int wm = (w >> 2) * 64, wn = (w & 3) * 32;

    float c[4][4][4];
#pragma unroll
    for (int mi = 0; mi < 4; mi++)
#pragma unroll
        for (int ni = 0; ni < 4; ni++)
#pragma unroll
            for (int q = 0; q < 4; q++) c[mi][ni][q] = 0.f;

    float4 pa0 = *(const float4*)(Ag + (size_t)lr * NI + lc);
    float4 pa1 = *(const float4*)(Ag + (size_t)(lr + 64) * NI + lc);
    float4 pb0 = *(const float4*)(Bg + (size_t)lr * NI + lc);
    float4 pb1 = *(const float4*)(Bg + (size_t)(lr + 64) * NI + lc);

    for (int kk = 0; kk < NI; kk += 16) {
        *(float4*)&As[lr * 20 + lc] = make_float4(tf32r(pa0.x), tf32r(pa0.y), tf32r(pa0.z), tf32r(pa0.w));
        *(float4*)&As[(lr + 64) * 20 + lc] = make_float4(tf32r(pa1.x), tf32r(pa1.y), tf32r(pa1.z), tf32r(pa1.w));
        *(float4*)&Bs2[lr * 20 + lc] = make_float4(tf32r(pb0.x), tf32r(pb0.y), tf32r(pb0.z), tf32r(pb0.w));
        *(float4*)&Bs2[(lr + 64) * 20 + lc] = make_float4(tf32r(pb1.x), tf32r(pb1.y), tf32r(pb1.z), tf32r(pb1.w));
        __syncthreads();
        if (kk + 16 < NI) {
            pa0 = *(const float4*)(Ag + (size_t)lr * NI + kk + 16 + lc);
            pa1 = *(const float4*)(Ag + (size_t)(lr + 64) * NI + kk + 16 + lc);
            pb0 = *(const float4*)(Bg + (size_t)lr * NI + kk + 16 + lc);
            pb1 = *(const float4*)(Bg + (size_t)(lr + 64) * NI + kk + 16 + lc);
        }
#pragma unroll
        for (int k8 = 0; k8 < 16; k8 += 8) {
            unsigned a[4][4], b[4][2];
#pragma unroll
            for (int mi = 0; mi < 4; mi++) {
                int rb = wm + mi * 16 + gid;
                a[mi][0] = fu(As[rb * 20 + k8 + tig]);
                a[mi][1] = fu(As[(rb + 8) * 20 + k8 + tig]);
                a[mi][2] = fu(As[rb * 20 + k8 + 4 + tig]);
                a[mi][3] = fu(As[(rb + 8) * 20 + k8 + 4 + tig]);
            }
#pragma unroll
            for (int ni = 0; ni < 4; ni++) {
                int nb = wn + ni * 8 + gid;
                b[ni][0] = fu(Bs2[nb * 20 + k8 + tig]);
                b[ni][1] = fu(Bs2[nb * 20 + k8 + 4 + tig]);
            }
#pragma unroll
            for (int mi = 0; mi < 4; mi++)
#pragma unroll
                for (int ni = 0; ni < 4; ni++) mma8(c[mi][ni], a[mi], b[ni]);
        }
        __syncthreads();
    }

#pragma unroll
    for (int mi = 0; mi < 4; mi++)
#pragma unroll
        for (int ni = 0; ni < 4; ni++) {
            int r = row0 + wm + mi * 16 + gid;
            int col = n0 + wn + ni * 8 + tig * 2;
            float b0 = g_bias[col], b1 = g_bias[col + 1];
            size_t o = (size_t)r * NG + col;
            g_Z[o] = c[mi][ni][0] + b0;
            g_Z[o + 1] = c[mi][ni][1] + b1;
            o += (size_t)8 * NG;
            g_Z[o] = c[mi][ni][2] + b0;
            g_Z[o + 1] = c[mi][ni][3] + b1;
        }
}

// ---------------- persistent recurrent kernel ----------------
// Block b = (gate-group gg = b>>1, batch-half hb = b&1).
// Covers gate cols [64gg, 64gg+64) (units 16gg..16gg+16) x batches [64hb, 64hb+64).
// Warp w owns K-chunk [128w,128w+128) = 8 k16 slots; fp16 Whh frags in registers.
// Barrier: decentralized flags — parallel release writes, per-thread polling.
__global__ __launch_bounds__(256, 1) void lstm_persistent(float* __restrict__ out,
                                                          const float* __restrict__ Whh,
                                                          const float* __restrict__ c0f,
                                                          const float* __restrict__ c0b) {
    extern __shared__ float smdyn[];
    float* part = smdyn;             // 64 gate-cols x PS2 ; part[gc*PS2 + ml*8 + w]
    float* zs = smdyn + 64 * PS2;    // 4096 floats: staged Z (i,f,g,o per item)

    const int b = blockIdx.x, tid = threadIdx.x;
    const int gg = b >> 1, hb = b & 1;
    const int w = tid >> 5, lane = tid & 31, gid = lane >> 2, tig = lane & 3;

    // one-time: fp16 A fragments (gate-permuted Whh rows) into registers
    unsigned Areg[4][8][4];
#pragma unroll
    for (int mt = 0; mt < 4; mt++)
#pragma unroll
        for (int ks = 0; ks < 8; ks++)
#pragma unroll
            for (int q = 0; q < 4; q++) {
                int pr = gg * 64 + mt * 16 + gid + 8 * (q & 1);  // gate-interleaved row
                int orow = (pr & 3) * NH + (pr >> 2);            // original Whh row
                int kc = (w * 8 + ks) * 16 + 2 * tig + 8 * (q >> 1);
                Areg[mt][ks][q] = h2u(__floats2half2_rn(Whh[(size_t)orow * NH + kc],
                                                        Whh[(size_t)orow * NH + kc + 1]));
            }

    // C state: item it -> (ml = (it*256+tid)>>4, ul = (it*256+tid)&15)
    float Creg[4];
#pragma unroll
    for (int it = 0; it < 4; it++) {
        int idx = it * 256 + tid, ml = idx >> 4, ul = idx & 15, j = gg * 16 + ul;
        Creg[it] = hb ? c0b[ml * NH + j] : c0f[ml * NH + j];
    }

    const size_t OB = (size_t)NB * NT * 2048;
    // lane-constant base into H records (halves): kslot = 8w, m = 64*hb + gid
    const size_t hlane = ((size_t)w * 8 * 128 + 64 * hb + gid) * 16 + tig * 4;

    for (int t = 0; t < NT; t++) {
        const __half* Hb = g_Hfrag + (size_t)(t & 1) * 131072 + hlane;

        // stage Z into smem (DRAM latency hidden under the K-loop)
#pragma unroll
        for (int it = 0; it < 4; it++) {
            int idx = it * 256 + tid, ml = idx >> 4, ul = idx & 15;
            size_t zrow = hb ? ((size_t)ml * NT + (NT - 1 - t)) : ((size_t)ml * NT + t);
            float4 z = __ldcs((const float4*)&g_Z[zrow * NG + gg * 64 + ul * 4]);
            *(float4*)&zs[idx * 4] = z;
        }

        // ---- main loop: 8 nt-tiles; 8 loads feed 32 MMAs per tile ----
        uint2 fb[2][8];
#pragma unroll
        for (int ks = 0; ks < 8; ks++)
            fb[0][ks] = __ldcg((const uint2*)(Hb + (size_t)ks * 2048));
#pragma unroll
        for (int nt = 0; nt < 8; nt++) {
            const int cur = nt & 1;
            if (nt < 7) {
#pragma unroll
                for (int ks = 0; ks < 8; ks++)
                    fb[cur ^ 1][ks] = __ldcg((const uint2*)(Hb + (size_t)ks * 2048 + (nt + 1) * 128));
            }
            float acc[4][4];
#pragma unroll
            for (int mt = 0; mt < 4; mt++)
#pragma unroll
                for (int q = 0; q < 4; q++) acc[mt][q] = 0.f;
#pragma unroll
            for (int ks = 0; ks < 8; ks++) {
                uint2 bb = fb[cur][ks];
                mma16(acc[0], Areg[0][ks], bb.x, bb.y);
                mma16(acc[1], Areg[1][ks], bb.x, bb.y);
                mma16(acc[2], Areg[2][ks], bb.x, bb.y);
                mma16(acc[3], Areg[3][ks], bb.x, bb.y);
            }
            int mb = nt * 8 + 2 * tig;
#pragma unroll
            for (int mt = 0; mt < 4; mt++) {
                int gc = mt * 16 + gid;
                part[gc * PS2 + mb * 8 + w] = acc[mt][0];
                part[gc * PS2 + (mb + 1) * 8 + w] = acc[mt][1];
                part[(gc + 8) * PS2 + mb * 8 + w] = acc[mt][2];
                part[(gc + 8) * PS2 + (mb + 1) * 8 + w] = acc[mt][3];
            }
        }
        __syncthreads();

        // ---- epilogue: reduce 8 partials + LSTM pointwise ----
        __half* Hn = g_Hfrag + (size_t)((t + 1) & 1) * 131072;
#pragma unroll
        for (int it = 0; it < 4; it++) {
            int idx = it * 256 + tid, ml = idx >> 4, ul = idx & 15, j = gg * 16 + ul;
            int m = 64 * hb + ml;
            float s[4];
#pragma unroll
            for (int g = 0; g < 4; g++) {
                const float* p = &part[(4 * ul + g) * PS2 + ml * 8];
                float4 p0 = *(const float4*)p;
                float4 p1 = *(const float4*)(p + 4);
                s[g] = ((p0.x + p0.y) + (p0.z + p0.w)) + ((p1.x + p1.y) + (p1.z + p1.w));
            }
            float4 z = *(const float4*)&zs[idx * 4];
            float iv = sigmf_(s[0] + z.x);
            float fv = sigmf_(s[1] + z.y);
            float gv = tanhf(s[2] + z.z);
            float ov = sigmf_(s[3] + z.w);
            float cv = fv * Creg[it] + iv * gv;
            Creg[it] = cv;
            float h = ov * tanhf(cv);
            Hn[(size_t)(gg * 128 + m) * 16 + hidx_of(ul)] = __float2half_rn(h);
            if (hb == 0) {
                out[((size_t)ml * NT + t) * 2048 + j] = h;
                out[((size_t)(63 - ml) * NT + t) * 2048 + 1024 + j] = h;
                if (t == NT - 1) out[OB + (size_t)ml * 2048 + j] = h;
            } else if (t == NT - 1) {
                out[OB + (size_t)ml * 2048 + 1024 + j] = h;
            }
        }

        // ---- decentralized flag barrier ----
        __syncthreads();                      // all epilogue work done (H written)
        if (tid == 0) {
            __threadfence();                  // release: H writes visible first
            *(volatile int*)&g_flags[b * 32] = t + 1;
        }
        if (tid < NBLK) {
            while (__ldcg(&g_flags[tid * 32]) < t + 1) { __nanosleep(20); }
            __threadfence();                  // acquire
        }
        __syncthreads();                      // also protects part/zs reuse
    }

    // c_i from registers
#pragma unroll
    for (int it = 0; it < 4; it++) {
        int idx = it * 256 + tid, ml = idx >> 4, ul = idx & 15, j = gg * 16 + ul;
        out[OB + 131072 + (size_t)ml * 2048 + hb * 1024 + j] = Creg[it];
    }
}

extern "C" void kernel_launch(void* const* d_in, const int* in_sizes, int n_in,
                              void* d_out, int out_size) {
    const float* x     = (const float*)d_in[0];
    const float* Wih_f = (const float*)d_in[1];
    const float* Whh_f = (const float*)d_in[2];
    const float* bih_f = (const float*)d_in[3];
    const float* bhh_f = (const float*)d_in[4];
    // d_in[5..8] (_b weights) are unused by the reference computation.
    const float* h0f   = (const float*)d_in[9];
    const float* c0f   = (const float*)d_in[10];
    const float* h0b   = (const float*)d_in[11];
    const float* c0b   = (const float*)d_in[12];
    float* out = (float*)d_out;

    const int smem_bytes = (64 * PS2 + 4096) * 4;   // 148480
    cudaFuncSetAttribute(lstm_persistent, cudaFuncAttributeMaxDynamicSharedMemorySize, smem_bytes);

    prep_all<<<(NG * NI) / 256, 256>>>(Wih_f, bih_f, bhh_f, h0f, h0b);

    dim3 zg(NG / 128, (NB * NT) / 128);   // (32, 256)
    zproj_kernel<<<zg, 256>>>(x);

    lstm_persistent<<<NBLK, 256, smem_bytes>>>(out, Whh_f, c0f, c0b);
}